// round 1
// baseline (speedup 1.0000x reference)
#include <cuda_runtime.h>

// SSIM loss: B=64, C=1, H=W=384, WIN=7 valid box filters -> 378x378 maps,
// scalar output = 1 - mean(SSIM).
//
// Fused single-pass design:
//   grid = (3 col strips) x (3 row bands) x (64 images), 128 threads/CTA.
//   Each thread owns one output column. Per 7-row step: stage 7 input rows of
//   X and Y into SMEM, compute per-row 7-tap horizontal sums (Sx,Sy,Sxx,Sxy,Syy)
//   in registers, maintain a 7-deep register ring (static indices via full
//   unroll) and running vertical window sums (add new / subtract 7-ago).
//   Emit SSIM per output pixel, accumulate, block-reduce, atomicAdd(double).

#define BATCH   64
#define HH      384
#define WW      384
#define WIN     7
#define OH      (HH - WIN + 1)   // 378
#define OW      (WW - WIN + 1)   // 378
#define STRIP   128
#define BAND    128
#define NSTRIPS 3
#define NBANDS  3
#define INW     (STRIP + WIN - 1)   // 134
#define INW_PAD (INW + 2)           // 136
#define NTHREADS 128

__device__ double g_acc;

__global__ void ssim_init_kernel() { g_acc = 0.0; }

__global__ __launch_bounds__(NTHREADS) void ssim_main_kernel(
    const float* __restrict__ X, const float* __restrict__ Y,
    const float* __restrict__ data_range)
{
    __shared__ float xb[WIN][INW_PAD];
    __shared__ float yb[WIN][INW_PAD];
    __shared__ float warpsum[NTHREADS / 32];

    const int t     = threadIdx.x;
    const int strip = blockIdx.x;
    const int band  = blockIdx.y;
    const int b     = blockIdx.z;

    const int col0 = strip * STRIP;
    const int row0 = band * BAND;
    const int rows_in = min(HH - row0, BAND + WIN - 1);  // 134 or 128
    const int ocol = col0 + t;
    const bool colvalid = (ocol < OW);

    const float L  = data_range[b];
    const float C1 = (0.01f * L) * (0.01f * L);
    const float C2 = (0.03f * L) * (0.03f * L);
    const float inv49 = 1.0f / 49.0f;
    const float covn  = 49.0f / 48.0f;

    const float* __restrict__ Xb = X + (size_t)b * HH * WW;
    const float* __restrict__ Yb = Y + (size_t)b * HH * WW;

    // 7-deep ring of horizontal window sums (static indexing via unroll)
    float hx[WIN], hy[WIN], hxx[WIN], hxy[WIN], hyy[WIN];
#pragma unroll
    for (int i = 0; i < WIN; i++) { hx[i]=0.f; hy[i]=0.f; hxx[i]=0.f; hxy[i]=0.f; hyy[i]=0.f; }

    // running vertical window sums
    float Wx=0.f, Wy=0.f, Wxx=0.f, Wxy=0.f, Wyy=0.f;
    float acc = 0.f;

    for (int r0 = 0; r0 < rows_in; r0 += WIN) {
        const int nrows = min(WIN, rows_in - r0);

        // Stage nrows input rows (cols col0 .. col0+133, zero-padded past W).
        for (int e = t; e < nrows * INW; e += NTHREADS) {
            const int rr = e / INW;
            const int cc = e - rr * INW;
            const int gr = row0 + r0 + rr;           // < H guaranteed
            const int gc = col0 + cc;
            float xv = 0.f, yv = 0.f;
            if (gc < WW) {
                const size_t idx = (size_t)gr * WW + gc;
                xv = Xb[idx];
                yv = Yb[idx];
            }
            xb[rr][cc] = xv;
            yb[rr][cc] = yv;
        }
        __syncthreads();

#pragma unroll
        for (int i = 0; i < WIN; i++) {
            if (i < nrows) {
                // 7-tap horizontal window sums for this thread's column
                float sx=0.f, sy=0.f, sxx=0.f, sxy=0.f, syy=0.f;
#pragma unroll
                for (int k = 0; k < WIN; k++) {
                    const float x = xb[i][t + k];
                    const float y = yb[i][t + k];
                    sx += x; sy += y;
                    sxx = fmaf(x, x, sxx);
                    sxy = fmaf(x, y, sxy);
                    syy = fmaf(y, y, syy);
                }
                // vertical running sums, ring slot i == (r0+i) % 7
                Wx  += sx  - hx[i];  hx[i]  = sx;
                Wy  += sy  - hy[i];  hy[i]  = sy;
                Wxx += sxx - hxx[i]; hxx[i] = sxx;
                Wxy += sxy - hxy[i]; hxy[i] = sxy;
                Wyy += syy - hyy[i]; hyy[i] = syy;

                const int r = r0 + i;   // local input row index
                if (r >= WIN - 1 && colvalid) {
                    const float ux  = Wx  * inv49;
                    const float uy  = Wy  * inv49;
                    const float uxx = Wxx * inv49;
                    const float uxy = Wxy * inv49;
                    const float uyy = Wyy * inv49;
                    const float vx  = covn * (uxx - ux * ux);
                    const float vy  = covn * (uyy - uy * uy);
                    const float vxy = covn * (uxy - ux * uy);
                    const float N1 = 2.0f * ux * uy + C1;
                    const float N2 = 2.0f * vxy + C2;
                    const float D1 = ux * ux + uy * uy + C1;
                    const float D2 = vx + vy + C2;
                    acc += __fdividef(N1 * N2, D1 * D2);
                }
            }
        }
        __syncthreads();
    }

    // block reduction -> global double accumulator
#pragma unroll
    for (int o = 16; o > 0; o >>= 1)
        acc += __shfl_xor_sync(0xffffffffu, acc, o);
    if ((t & 31) == 0) warpsum[t >> 5] = acc;
    __syncthreads();
    if (t == 0) {
        float s = warpsum[0] + warpsum[1] + warpsum[2] + warpsum[3];
        atomicAdd(&g_acc, (double)s);
    }
}

__global__ void ssim_final_kernel(float* __restrict__ out)
{
    out[0] = (float)(1.0 - g_acc / ((double)BATCH * OH * OW));
}

extern "C" void kernel_launch(void* const* d_in, const int* in_sizes, int n_in,
                              void* d_out, int out_size)
{
    const float* X  = (const float*)d_in[0];
    const float* Y  = (const float*)d_in[1];
    const float* dr = (const float*)d_in[2];
    float* out = (float*)d_out;

    ssim_init_kernel<<<1, 1>>>();
    dim3 grid(NSTRIPS, NBANDS, BATCH);
    ssim_main_kernel<<<grid, NTHREADS>>>(X, Y, dr);
    ssim_final_kernel<<<1, 1>>>(out);
}

// round 2
// speedup vs baseline: 1.9651x; 1.9651x over previous
#include <cuda_runtime.h>

// SSIM loss, fused single pass. B=64, H=W=384, WIN=7 -> 378x378 maps, scalar out.
//
// R2 design:
//  - CTA covers the FULL image width: 192 threads x 2 output columns = 384.
//  - Grid = (6 row bands) x (64 images) = 384 CTAs. 63 output rows per band.
//  - Per 7-row step: stage 7 full rows of X,Y to SMEM via float4, then each
//    thread computes 7-tap horizontal sums for its 2 columns (col1 slides off
//    col0), maintains 7-deep register rings (static idx via unroll) and
//    running vertical sums, emits SSIM for 2 pixels/row.
//  - No init kernel: per-CTA partial -> g_part[384], final kernel reduces.

#define BATCH    64
#define HH       384
#define WW       384
#define WIN      7
#define OH       378
#define OW       378
#define NBANDS   6
#define OROWS    (OH / NBANDS)          // 63 output rows per band
#define INROWS   (OROWS + WIN - 1)      // 69 input rows per band
#define NTHREADS 192
#define ROWPAD   392                    // 384 + 8 pad (16B-aligned pitch)
#define NF4      (WW / 4)               // 96 float4 per row

__device__ float g_part[NBANDS * BATCH];

__global__ __launch_bounds__(NTHREADS) void ssim_main_kernel(
    const float* __restrict__ X, const float* __restrict__ Y,
    const float* __restrict__ data_range)
{
    __shared__ float xb[WIN][ROWPAD];
    __shared__ float yb[WIN][ROWPAD];
    __shared__ float warpsum[NTHREADS / 32];

    const int t    = threadIdx.x;
    const int band = blockIdx.x;
    const int b    = blockIdx.y;
    const int row0 = band * OROWS;
    const int c    = 2 * t;
    const bool v0 = (c < OW);
    const bool v1 = (c + 1 < OW);

    const float L  = data_range[b];
    const float C1 = (0.01f * L) * (0.01f * L);
    const float C2 = (0.03f * L) * (0.03f * L);
    const float inv49 = 1.0f / 49.0f;
    const float covn  = 49.0f / 48.0f;

    const float* __restrict__ Xb = X + (size_t)b * HH * WW;
    const float* __restrict__ Yb = Y + (size_t)b * HH * WW;

    // rings: [stat][slot][col] flattened; static indexing only (full unroll)
    float rx0[WIN], rx1[WIN], ry0[WIN], ry1[WIN];
    float rxx0[WIN], rxx1[WIN], rxy0[WIN], rxy1[WIN], ryy0[WIN], ryy1[WIN];
#pragma unroll
    for (int i = 0; i < WIN; i++) {
        rx0[i]=0.f; rx1[i]=0.f; ry0[i]=0.f; ry1[i]=0.f;
        rxx0[i]=0.f; rxx1[i]=0.f; rxy0[i]=0.f; rxy1[i]=0.f; ryy0[i]=0.f; ryy1[i]=0.f;
    }
    float Wx0=0.f, Wx1=0.f, Wy0=0.f, Wy1=0.f;
    float Wxx0=0.f, Wxx1=0.f, Wxy0=0.f, Wxy1=0.f, Wyy0=0.f, Wyy1=0.f;
    float acc = 0.f;

    for (int r0 = 0; r0 < INROWS; r0 += WIN) {
        const int nrows = min(WIN, INROWS - r0);

        // ---- stage nrows full rows of X and Y via float4 ----
        {
            const float4* __restrict__ Xr = (const float4*)(Xb + (size_t)(row0 + r0) * WW);
            const float4* __restrict__ Yr = (const float4*)(Yb + (size_t)(row0 + r0) * WW);
            const int total = nrows * NF4;
            for (int e = t; e < total; e += NTHREADS) {
                const int rr = e / NF4;
                const int cc = e - rr * NF4;
                *(float4*)&xb[rr][cc * 4] = Xr[e];
                *(float4*)&yb[rr][cc * 4] = Yr[e];
            }
        }
        __syncthreads();

#pragma unroll
        for (int i = 0; i < WIN; i++) {
            if (i < nrows) {
                // load 8 x-values and 8 y-values covering cols c..c+7
                float2 a0 = *(const float2*)&xb[i][c];
                float2 a1 = *(const float2*)&xb[i][c + 2];
                float2 a2 = *(const float2*)&xb[i][c + 4];
                float2 a3 = *(const float2*)&xb[i][c + 6];
                float2 b0 = *(const float2*)&yb[i][c];
                float2 b1 = *(const float2*)&yb[i][c + 2];
                float2 b2 = *(const float2*)&yb[i][c + 4];
                float2 b3 = *(const float2*)&yb[i][c + 6];
                const float x0=a0.x, x1=a0.y, x2=a1.x, x3=a1.y, x4=a2.x, x5=a2.y, x6=a3.x, x7=a3.y;
                const float y0=b0.x, y1=b0.y, y2=b1.x, y3=b1.y, y4=b2.x, y5=b2.y, y6=b3.x, y7=b3.y;

                // 7-tap sums, col0 direct, col1 via slide
                const float sx0 = ((x0+x1)+(x2+x3)) + ((x4+x5)+x6);
                const float sx1 = sx0 - x0 + x7;
                const float sy0 = ((y0+y1)+(y2+y3)) + ((y4+y5)+y6);
                const float sy1 = sy0 - y0 + y7;
                float sxx0 = x0*x0; sxx0=fmaf(x1,x1,sxx0); sxx0=fmaf(x2,x2,sxx0);
                sxx0=fmaf(x3,x3,sxx0); sxx0=fmaf(x4,x4,sxx0); sxx0=fmaf(x5,x5,sxx0); sxx0=fmaf(x6,x6,sxx0);
                const float sxx1 = sxx0 + fmaf(x7, x7, -(x0*x0));
                float sxy0 = x0*y0; sxy0=fmaf(x1,y1,sxy0); sxy0=fmaf(x2,y2,sxy0);
                sxy0=fmaf(x3,y3,sxy0); sxy0=fmaf(x4,y4,sxy0); sxy0=fmaf(x5,y5,sxy0); sxy0=fmaf(x6,y6,sxy0);
                const float sxy1 = sxy0 + fmaf(x7, y7, -(x0*y0));
                float syy0 = y0*y0; syy0=fmaf(y1,y1,syy0); syy0=fmaf(y2,y2,syy0);
                syy0=fmaf(y3,y3,syy0); syy0=fmaf(y4,y4,syy0); syy0=fmaf(y5,y5,syy0); syy0=fmaf(y6,y6,syy0);
                const float syy1 = syy0 + fmaf(y7, y7, -(y0*y0));

                // vertical running windows (ring slot == i, since step == WIN)
                Wx0  += sx0  - rx0[i];  rx0[i]  = sx0;
                Wx1  += sx1  - rx1[i];  rx1[i]  = sx1;
                Wy0  += sy0  - ry0[i];  ry0[i]  = sy0;
                Wy1  += sy1  - ry1[i];  ry1[i]  = sy1;
                Wxx0 += sxx0 - rxx0[i]; rxx0[i] = sxx0;
                Wxx1 += sxx1 - rxx1[i]; rxx1[i] = sxx1;
                Wxy0 += sxy0 - rxy0[i]; rxy0[i] = sxy0;
                Wxy1 += sxy1 - rxy1[i]; rxy1[i] = sxy1;
                Wyy0 += syy0 - ryy0[i]; ryy0[i] = syy0;
                Wyy1 += syy1 - ryy1[i]; ryy1[i] = syy1;

                const int r = r0 + i;
                if (r >= WIN - 1) {
                    if (v0) {
                        const float ux  = Wx0  * inv49;
                        const float uy  = Wy0  * inv49;
                        const float vx  = covn * fmaf(Wxx0, inv49, -(ux * ux));
                        const float vy  = covn * fmaf(Wyy0, inv49, -(uy * uy));
                        const float vxy = covn * fmaf(Wxy0, inv49, -(ux * uy));
                        const float N1 = 2.0f * ux * uy + C1;
                        const float N2 = 2.0f * vxy + C2;
                        const float D1 = ux * ux + uy * uy + C1;
                        const float D2 = vx + vy + C2;
                        acc += __fdividef(N1 * N2, D1 * D2);
                    }
                    if (v1) {
                        const float ux  = Wx1  * inv49;
                        const float uy  = Wy1  * inv49;
                        const float vx  = covn * fmaf(Wxx1, inv49, -(ux * ux));
                        const float vy  = covn * fmaf(Wyy1, inv49, -(uy * uy));
                        const float vxy = covn * fmaf(Wxy1, inv49, -(ux * uy));
                        const float N1 = 2.0f * ux * uy + C1;
                        const float N2 = 2.0f * vxy + C2;
                        const float D1 = ux * ux + uy * uy + C1;
                        const float D2 = vx + vy + C2;
                        acc += __fdividef(N1 * N2, D1 * D2);
                    }
                }
            }
        }
        __syncthreads();
    }

    // block reduction -> per-CTA partial (no atomics, no init kernel)
#pragma unroll
    for (int o = 16; o > 0; o >>= 1)
        acc += __shfl_xor_sync(0xffffffffu, acc, o);
    if ((t & 31) == 0) warpsum[t >> 5] = acc;
    __syncthreads();
    if (t == 0) {
        float s = 0.f;
#pragma unroll
        for (int w = 0; w < NTHREADS / 32; w++) s += warpsum[w];
        g_part[b * NBANDS + band] = s;
    }
}

__global__ __launch_bounds__(128) void ssim_final_kernel(float* __restrict__ out)
{
    __shared__ double sm[4];
    const int t = threadIdx.x;
    double s = 0.0;
    for (int i = t; i < NBANDS * BATCH; i += 128) s += (double)g_part[i];
#pragma unroll
    for (int o = 16; o > 0; o >>= 1)
        s += __shfl_xor_sync(0xffffffffu, s, o);
    if ((t & 31) == 0) sm[t >> 5] = s;
    __syncthreads();
    if (t == 0) {
        double tot = sm[0] + sm[1] + sm[2] + sm[3];
        out[0] = (float)(1.0 - tot / ((double)BATCH * OH * OW));
    }
}

extern "C" void kernel_launch(void* const* d_in, const int* in_sizes, int n_in,
                              void* d_out, int out_size)
{
    const float* X  = (const float*)d_in[0];
    const float* Y  = (const float*)d_in[1];
    const float* dr = (const float*)d_in[2];
    float* out = (float*)d_out;

    dim3 grid(NBANDS, BATCH);
    ssim_main_kernel<<<grid, NTHREADS>>>(X, Y, dr);
    ssim_final_kernel<<<1, 128>>>(out);
}

// round 3
// speedup vs baseline: 2.3400x; 1.1908x over previous
#include <cuda_runtime.h>

// SSIM loss, fused single pass + fused finalize. B=64, H=W=384, WIN=7.
//
// R3:
//  - 192 threads x 2 cols = full 384-wide row per CTA; 9 row bands x 64 images.
//  - Register ring sliding-window (7-deep, static idx) for 5 window stats x 2 cols.
//  - Divide amortization: 2 cols combined into one rational, consecutive output
//    rows paired -> 1 MUFU.RCP per 4 pixels (was 1 per pixel).
//  - Scale-free SSIM: constants pre-multiplied by 49^2, no per-stat /49.
//  - Last-block finalize (atomic counter, self-resetting, deterministic order).

#define BATCH    64
#define HH       384
#define WW       384
#define WIN      7
#define OH       378
#define OW       378
#define NBANDS   9
#define OROWS    (OH / NBANDS)          // 42 output rows per band
#define INROWS   (OROWS + WIN - 1)      // 48 input rows per band
#define NTHREADS 192
#define ROWPAD   392
#define NF4      (WW / 4)               // 96 float4 per row
#define NCTAS    (NBANDS * BATCH)       // 576

__device__ float g_part[NCTAS];
__device__ unsigned int g_count;        // zero-init; last block resets to 0

__global__ __launch_bounds__(NTHREADS, 2) void ssim_main_kernel(
    const float* __restrict__ X, const float* __restrict__ Y,
    const float* __restrict__ data_range, float* __restrict__ out)
{
    __shared__ float xb[WIN][ROWPAD];
    __shared__ float yb[WIN][ROWPAD];
    __shared__ float warpsum[NTHREADS / 32];
    __shared__ int is_last;

    const int t    = threadIdx.x;
    const int band = blockIdx.x;
    const int b    = blockIdx.y;
    const int row0 = band * OROWS;
    const int c    = 2 * t;
    const bool valid = (c + 1 < OW);    // threads 0..188: both cols valid

    const float L   = data_range[b];
    const float C1s = (0.49f * L) * (0.49f * L);     // C1 * 49^2
    const float C2s = (1.47f * L) * (1.47f * L);     // C2 * 49^2
    const float covn  = 49.0f / 48.0f;
    const float covn2 = 2.0f * covn;

    const float* __restrict__ Xb = X + (size_t)b * HH * WW;
    const float* __restrict__ Yb = Y + (size_t)b * HH * WW;

    float rx0[WIN], rx1[WIN], ry0[WIN], ry1[WIN];
    float rxx0[WIN], rxx1[WIN], rxy0[WIN], rxy1[WIN], ryy0[WIN], ryy1[WIN];
#pragma unroll
    for (int i = 0; i < WIN; i++) {
        rx0[i]=0.f; rx1[i]=0.f; ry0[i]=0.f; ry1[i]=0.f;
        rxx0[i]=0.f; rxx1[i]=0.f; rxy0[i]=0.f; rxy1[i]=0.f; ryy0[i]=0.f; ryy1[i]=0.f;
    }
    float Wx0=0.f, Wx1=0.f, Wy0=0.f, Wy1=0.f;
    float Wxx0=0.f, Wxx1=0.f, Wxy0=0.f, Wxy1=0.f, Wyy0=0.f, Wyy1=0.f;
    float acc = 0.f;
    float pn = 0.f, pd = 1.f;
    bool  have = false;

    for (int r0 = 0; r0 < INROWS; r0 += WIN) {
        const int nrows = min(WIN, INROWS - r0);

        {
            const float4* __restrict__ Xr = (const float4*)(Xb + (size_t)(row0 + r0) * WW);
            const float4* __restrict__ Yr = (const float4*)(Yb + (size_t)(row0 + r0) * WW);
            const int total = nrows * NF4;
            for (int e = t; e < total; e += NTHREADS) {
                const int rr = e / NF4;
                const int cc = e - rr * NF4;
                *(float4*)&xb[rr][cc * 4] = Xr[e];
                *(float4*)&yb[rr][cc * 4] = Yr[e];
            }
        }
        __syncthreads();

#pragma unroll
        for (int i = 0; i < WIN; i++) {
            if (i < nrows) {
                float2 a0 = *(const float2*)&xb[i][c];
                float2 a1 = *(const float2*)&xb[i][c + 2];
                float2 a2 = *(const float2*)&xb[i][c + 4];
                float2 a3 = *(const float2*)&xb[i][c + 6];
                float2 b0 = *(const float2*)&yb[i][c];
                float2 b1 = *(const float2*)&yb[i][c + 2];
                float2 b2 = *(const float2*)&yb[i][c + 4];
                float2 b3 = *(const float2*)&yb[i][c + 6];
                const float x0=a0.x, x1=a0.y, x2=a1.x, x3=a1.y, x4=a2.x, x5=a2.y, x6=a3.x, x7=a3.y;
                const float y0=b0.x, y1=b0.y, y2=b1.x, y3=b1.y, y4=b2.x, y5=b2.y, y6=b3.x, y7=b3.y;

                const float sx0 = ((x0+x1)+(x2+x3)) + ((x4+x5)+x6);
                const float sx1 = sx0 - x0 + x7;
                const float sy0 = ((y0+y1)+(y2+y3)) + ((y4+y5)+y6);
                const float sy1 = sy0 - y0 + y7;
                float sxx0 = x0*x0; sxx0=fmaf(x1,x1,sxx0); sxx0=fmaf(x2,x2,sxx0);
                sxx0=fmaf(x3,x3,sxx0); sxx0=fmaf(x4,x4,sxx0); sxx0=fmaf(x5,x5,sxx0); sxx0=fmaf(x6,x6,sxx0);
                const float sxx1 = sxx0 + fmaf(x7, x7, -(x0*x0));
                float sxy0 = x0*y0; sxy0=fmaf(x1,y1,sxy0); sxy0=fmaf(x2,y2,sxy0);
                sxy0=fmaf(x3,y3,sxy0); sxy0=fmaf(x4,y4,sxy0); sxy0=fmaf(x5,y5,sxy0); sxy0=fmaf(x6,y6,sxy0);
                const float sxy1 = sxy0 + fmaf(x7, y7, -(x0*y0));
                float syy0 = y0*y0; syy0=fmaf(y1,y1,syy0); syy0=fmaf(y2,y2,syy0);
                syy0=fmaf(y3,y3,syy0); syy0=fmaf(y4,y4,syy0); syy0=fmaf(y5,y5,syy0); syy0=fmaf(y6,y6,syy0);
                const float syy1 = syy0 + fmaf(y7, y7, -(y0*y0));

                Wx0  += sx0  - rx0[i];  rx0[i]  = sx0;
                Wx1  += sx1  - rx1[i];  rx1[i]  = sx1;
                Wy0  += sy0  - ry0[i];  ry0[i]  = sy0;
                Wy1  += sy1  - ry1[i];  ry1[i]  = sy1;
                Wxx0 += sxx0 - rxx0[i]; rxx0[i] = sxx0;
                Wxx1 += sxx1 - rxx1[i]; rxx1[i] = sxx1;
                Wxy0 += sxy0 - rxy0[i]; rxy0[i] = sxy0;
                Wxy1 += sxy1 - rxy1[i]; rxy1[i] = sxy1;
                Wyy0 += syy0 - ryy0[i]; ryy0[i] = syy0;
                Wyy1 += syy1 - ryy1[i]; ryy1[i] = syy1;

                const int r = r0 + i;
                if (r >= WIN - 1 && valid) {
                    // scale-free SSIM (everything x 49^2 relative to means form)
                    // col 0
                    const float pxy0 = Wx0 * Wy0;
                    const float px20 = Wx0 * Wx0;
                    const float py20 = Wy0 * Wy0;
                    const float n1a = fmaf(2.0f, pxy0, C1s);
                    const float d1a = px20 + py20 + C1s;
                    const float n2a = fmaf(covn2, fmaf(49.0f, Wxy0, -pxy0), C2s);
                    const float d2a = fmaf(covn,
                        fmaf(49.0f, Wxx0, -px20) + fmaf(49.0f, Wyy0, -py20), C2s);
                    const float Na = n1a * n2a;
                    const float Da = d1a * d2a;
                    // col 1
                    const float pxy1 = Wx1 * Wy1;
                    const float px21 = Wx1 * Wx1;
                    const float py21 = Wy1 * Wy1;
                    const float n1b = fmaf(2.0f, pxy1, C1s);
                    const float d1b = px21 + py21 + C1s;
                    const float n2b = fmaf(covn2, fmaf(49.0f, Wxy1, -pxy1), C2s);
                    const float d2b = fmaf(covn,
                        fmaf(49.0f, Wxx1, -px21) + fmaf(49.0f, Wyy1, -py21), C2s);
                    const float Nb = n1b * n2b;
                    const float Db = d1b * d2b;
                    // combine 2 cols into one rational
                    const float n2r = fmaf(Na, Db, Nb * Da);
                    const float d2r = Da * Db;
                    // pair with previous output row: 1 divide per 4 pixels
                    if (have) {
                        acc += __fdividef(fmaf(pn, d2r, n2r * pd), pd * d2r);
                        have = false;
                    } else {
                        pn = n2r; pd = d2r; have = true;
                    }
                }
            }
        }
        __syncthreads();
    }
    if (have && valid) acc += __fdividef(pn, pd);

    // block reduction -> per-CTA partial
#pragma unroll
    for (int o = 16; o > 0; o >>= 1)
        acc += __shfl_xor_sync(0xffffffffu, acc, o);
    if ((t & 31) == 0) warpsum[t >> 5] = acc;
    __syncthreads();
    const int cta = b * NBANDS + band;
    if (t == 0) {
        float s = 0.f;
#pragma unroll
        for (int w = 0; w < NTHREADS / 32; w++) s += warpsum[w];
        g_part[cta] = s;
        __threadfence();
        unsigned int n = atomicAdd(&g_count, 1u);
        is_last = (n == NCTAS - 1) ? 1 : 0;
    }
    __syncthreads();

    // last CTA performs the deterministic final reduction
    if (is_last) {
        __threadfence();
        double s = 0.0;
        s += (double)g_part[t];
        s += (double)g_part[t + NTHREADS];
        s += (double)g_part[t + 2 * NTHREADS];
#pragma unroll
        for (int o = 16; o > 0; o >>= 1)
            s += __shfl_xor_sync(0xffffffffu, s, o);
        __shared__ double dsum[NTHREADS / 32];
        if ((t & 31) == 0) dsum[t >> 5] = s;
        __syncthreads();
        if (t == 0) {
            double tot = 0.0;
#pragma unroll
            for (int w = 0; w < NTHREADS / 32; w++) tot += dsum[w];
            out[0] = (float)(1.0 - tot / ((double)BATCH * OH * OW));
            g_count = 0;   // reset for next graph replay
        }
    }
}

extern "C" void kernel_launch(void* const* d_in, const int* in_sizes, int n_in,
                              void* d_out, int out_size)
{
    const float* X  = (const float*)d_in[0];
    const float* Y  = (const float*)d_in[1];
    const float* dr = (const float*)d_in[2];
    float* out = (float*)d_out;

    dim3 grid(NBANDS, BATCH);
    ssim_main_kernel<<<grid, NTHREADS>>>(X, Y, dr, out);
}